// round 4
// baseline (speedup 1.0000x reference)
#include <cuda_runtime.h>
#include <cuda_bf16.h>

// Problem constants (fixed by setup_inputs)
#define BATCH 32
#define TSEQ  1024
#define DIM   512
#define NMAX  500000
#define MAXK  64

#define FULLMASK 0xffffffffu
#define NEG_BIG (-3.0e38f)

#define SEGLEN 16384            // elements per top-k phase-1 block
#define MAX_SEGS 64             // supports N up to 1M
#define W1 8                    // warps per phase-1 block

// ---------------- device scratch (no allocations allowed) ----------------
__device__ float g_part[BATCH * 8 * DIM];
__device__ float g_query[BATCH * DIM];
__device__ float g_scores[BATCH * NMAX];          // 64 MB
__device__ float g_cv[BATCH * MAX_SEGS * W1 * 64]; // phase-1 candidate values
__device__ int   g_ci[BATCH * MAX_SEGS * W1 * 64]; // phase-1 candidate indices
__device__ float g_topv[BATCH * MAXK];
__device__ int   g_topi[BATCH * MAXK];

// ---------------- kernel 1: partial mean over T ----------------
__global__ void k_pool_partial(const float* __restrict__ hidden) {
    int b = blockIdx.x >> 3;
    int chunk = blockIdx.x & 7;
    int tid = threadIdx.x;
    const float* base = hidden + ((size_t)b * TSEQ + chunk * 128) * DIM;
    float a0 = 0.f, a1 = 0.f;
#pragma unroll 4
    for (int t = 0; t < 128; ++t) {
        a0 += base[t * DIM + tid];
        a1 += base[t * DIM + tid + 256];
    }
    g_part[(b * 8 + chunk) * DIM + tid]       = a0;
    g_part[(b * 8 + chunk) * DIM + tid + 256] = a1;
}

// ---------------- kernel 2: query = mean @ W + b ----------------
__global__ void k_query(const float* __restrict__ W, const float* __restrict__ bias) {
    int b = blockIdx.x;
    int j = threadIdx.x;
    __shared__ float sp[DIM];
    float s = 0.f;
#pragma unroll
    for (int c = 0; c < 8; ++c) s += g_part[(b * 8 + c) * DIM + j];
    sp[j] = s * (1.0f / (float)TSEQ);
    __syncthreads();
    float q = bias[j];
#pragma unroll 8
    for (int d = 0; d < DIM; ++d) q += sp[d] * W[d * DIM + j];
    g_query[b * DIM + j] = q;
}

// ---------------- kernel 3: scores = (query @ keys^T) / sqrt(D) ----------------
// BN=512 keys x 32 batches per block, 256 threads, 8x8 register tile per thread.
#define BN 512
#define BK 64
#define KSTRIDE (BK + 2)   // 66 words; lane stride = 33 x 8B (odd) => conflict-free LDS.64

__device__ __forceinline__ unsigned long long f32x2_fma(unsigned long long a,
                                                        unsigned long long b,
                                                        unsigned long long c) {
    unsigned long long d;
    asm("fma.rn.f32x2 %0, %1, %2, %3;" : "=l"(d) : "l"(a), "l"(b), "l"(c));
    return d;
}

__global__ void __launch_bounds__(256, 1)
k_scores(const float* __restrict__ keys, int N) {
    extern __shared__ float smem[];
    float* qs = smem;                 // [32][512]
    float* ks = smem + BATCH * DIM;   // [BN][KSTRIDE]

    int tid = threadIdx.x;
    int tx = tid & 63;       // key group: 8 keys at tx + j*64
    int ty = tid >> 6;       // batch group: 8 batches at ty*8 + i
    int n0 = blockIdx.x * BN;

#pragma unroll
    for (int i = 0; i < (BATCH * DIM) / 256; ++i)
        qs[tid + i * 256] = g_query[tid + i * 256];

    unsigned long long acc[8][8];
#pragma unroll
    for (int i = 0; i < 8; ++i)
#pragma unroll
        for (int j = 0; j < 8; ++j) acc[i][j] = 0ull;

    for (int kt = 0; kt < DIM / BK; ++kt) {
        __syncthreads();
        // load tile: BN keys x BK floats = 8192 float4, 32 per thread
#pragma unroll
        for (int it = 0; it < 32; ++it) {
            int f = tid + it * 256;
            int key = f >> 4;          // BK/4 = 16 float4 per key
            int kq = f & 15;
            int gk = n0 + key;
            float4 v;
            if (gk < N) {
                v = *reinterpret_cast<const float4*>(&keys[(size_t)gk * DIM + kt * BK + kq * 4]);
            } else {
                v = make_float4(0.f, 0.f, 0.f, 0.f);
            }
            float2* dst = reinterpret_cast<float2*>(&ks[key * KSTRIDE + kq * 4]);
            dst[0] = make_float2(v.x, v.y);
            dst[1] = make_float2(v.z, v.w);
        }
        __syncthreads();

#pragma unroll 4
        for (int kp = 0; kp < BK; kp += 2) {
            unsigned long long kv[8], qv[8];
#pragma unroll
            for (int j = 0; j < 8; ++j)
                kv[j] = *reinterpret_cast<const unsigned long long*>(&ks[(tx + j * 64) * KSTRIDE + kp]);
#pragma unroll
            for (int i = 0; i < 8; ++i)
                qv[i] = *reinterpret_cast<const unsigned long long*>(&qs[(ty * 8 + i) * DIM + kt * BK + kp]);
#pragma unroll
            for (int i = 0; i < 8; ++i)
#pragma unroll
                for (int j = 0; j < 8; ++j)
                    acc[i][j] = f32x2_fma(qv[i], kv[j], acc[i][j]);
        }
    }

    const float scale = 1.0f / sqrtf((float)DIM);
#pragma unroll
    for (int i = 0; i < 8; ++i) {
        int b = ty * 8 + i;
#pragma unroll
        for (int j = 0; j < 8; ++j) {
            int n = n0 + tx + j * 64;
            if (n < N) {
                unsigned long long u = acc[i][j];
                float lo = __uint_as_float((unsigned)(u & 0xffffffffull));
                float hi = __uint_as_float((unsigned)(u >> 32));
                g_scores[(size_t)b * N + n] = (lo + hi) * scale;
            }
        }
    }
}

// ---------------- warp helpers ----------------
__device__ __forceinline__ float warp_min32(float v) {
#pragma unroll
    for (int o = 16; o; o >>= 1) v = fminf(v, __shfl_xor_sync(FULLMASK, v, o));
    return v;
}

// Insert a 4-element packet into the warp-shared top-64 (2 slots per lane).
__device__ __forceinline__ void topk_insert4(float a0, float a1, float a2, float a3,
                                             int base, float& v0, float& v1,
                                             int& i0, int& i1, float& thr) {
    unsigned pm = (unsigned)(a0 > thr) | ((unsigned)(a1 > thr) << 1) |
                  ((unsigned)(a2 > thr) << 2) | ((unsigned)(a3 > thr) << 3);
    while (__any_sync(FULLMASK, pm != 0)) {
        int c = __ffs(pm) - 1;
        float cv = (c == 0) ? a0 : (c == 1) ? a1 : (c == 2) ? a2 : a3;
        int ci = base + c;
        unsigned ball = __ballot_sync(FULLMASK, pm != 0);
        int src = __ffs(ball) - 1;
        float cand = __shfl_sync(FULLMASK, cv, src);
        int candi = __shfl_sync(FULLMASK, ci, src);
        int lane = threadIdx.x & 31;
        if (lane == src) pm &= pm - 1;
        if (cand > thr) {
            float mn = fminf(v0, v1);
            float wmn = warp_min32(mn);
            unsigned who = __ballot_sync(FULLMASK, mn == wmn);
            int wl = __ffs(who) - 1;
            if (lane == wl) {
                if (v0 <= v1) { v0 = cand; i0 = candi; }
                else          { v1 = cand; i1 = candi; }
            }
            thr = warp_min32(fminf(v0, v1));
        }
        if (pm) {
            if ((pm & 1u) && a0 <= thr) pm &= ~1u;
            if ((pm & 2u) && a1 <= thr) pm &= ~2u;
            if ((pm & 4u) && a2 <= thr) pm &= ~4u;
            if ((pm & 8u) && a3 <= thr) pm &= ~8u;
        }
    }
}

// ---------------- kernel 4a: per-segment warp top-64 candidates ----------------
// grid = BATCH * SEGS, 256 threads (8 warps). Each block covers SEGLEN elements.
__global__ void __launch_bounds__(256)
k_topk_part(int N, int segs) {
    int row = blockIdx.x / segs;
    int seg = blockIdx.x % segs;
    int tid = threadIdx.x;
    int lane = tid & 31;
    int wid = tid >> 5;

    const float* S = g_scores + (size_t)row * N;
    int s0 = seg * SEGLEN;

    float v0 = NEG_BIG, v1 = NEG_BIG;
    int i0 = 0, i1 = 0;
    float thr = NEG_BIG;

    // 8 iterations x 256 threads x 8 floats (two float4 loads batched -> MLP)
#pragma unroll 2
    for (int it = 0; it < SEGLEN / (256 * 8); ++it) {
        int f0 = s0 + ((it * 512 + tid) << 2);       // first float4 (elem index)
        int f1 = s0 + ((it * 512 + 256 + tid) << 2); // second float4
        float4 xa, xb;
        bool ok0 = (f0 + 3 < N), ok1 = (f1 + 3 < N);
        if (ok0) xa = *reinterpret_cast<const float4*>(S + f0);
        if (ok1) xb = *reinterpret_cast<const float4*>(S + f1);
        if (!ok0) {
            xa.x = (f0 + 0 < N) ? S[f0 + 0] : NEG_BIG;
            xa.y = (f0 + 1 < N) ? S[f0 + 1] : NEG_BIG;
            xa.z = (f0 + 2 < N) ? S[f0 + 2] : NEG_BIG;
            xa.w = (f0 + 3 < N) ? S[f0 + 3] : NEG_BIG;
        }
        if (!ok1) {
            xb.x = (f1 + 0 < N) ? S[f1 + 0] : NEG_BIG;
            xb.y = (f1 + 1 < N) ? S[f1 + 1] : NEG_BIG;
            xb.z = (f1 + 2 < N) ? S[f1 + 2] : NEG_BIG;
            xb.w = (f1 + 3 < N) ? S[f1 + 3] : NEG_BIG;
        }
        topk_insert4(xa.x, xa.y, xa.z, xa.w, f0, v0, v1, i0, i1, thr);
        topk_insert4(xb.x, xb.y, xb.z, xb.w, f1, v0, v1, i0, i1, thr);
    }

    // dump warp candidates
    size_t o = ((size_t)(row * segs + seg) * W1 + wid) * 64;
    g_cv[o + lane]      = v0;  g_ci[o + lane]      = i0;
    g_cv[o + 32 + lane] = v1;  g_ci[o + 32 + lane] = i1;
}

// ---------------- kernel 4b: merge candidates -> exact sorted top-64 ----------------
// grid = BATCH, 1024 threads
__global__ void __launch_bounds__(1024)
k_topk_merge(int segs) {
    int row = blockIdx.x;
    int tid = threadIdx.x;
    int lane = tid & 31;
    int wid = tid >> 5;

    int C = segs * W1 * 64;                  // candidates this row
    const float* CV = g_cv + (size_t)row * segs * W1 * 64;
    const int*   CI = g_ci + (size_t)row * segs * W1 * 64;

    float v0 = NEG_BIG, v1 = NEG_BIG;
    int i0 = 0, i1 = 0;
    float thr = NEG_BIG;

    int iters = (C + 4095) >> 12;            // 1024 threads x 4 per iter
    for (int it = 0; it < iters; ++it) {
        int f = (it << 12) + (tid << 2);
        float a0 = (f + 0 < C) ? CV[f + 0] : NEG_BIG;
        float a1 = (f + 1 < C) ? CV[f + 1] : NEG_BIG;
        float a2 = (f + 2 < C) ? CV[f + 2] : NEG_BIG;
        float a3 = (f + 3 < C) ? CV[f + 3] : NEG_BIG;
        // encode candidate slot; translate to original index on insert
        topk_insert4(a0, a1, a2, a3, f, v0, v1, i0, i1, thr);
    }
    // translate slots -> original indices
    i0 = (v0 > NEG_BIG) ? CI[i0] : 0;
    i1 = (v1 > NEG_BIG) ? CI[i1] : 0;

    __shared__ float sv[2048];
    __shared__ int   si[2048];
    __shared__ float wv[32];
    __shared__ int   wp[32];
    sv[wid * 64 + lane]      = v0;  si[wid * 64 + lane]      = i0;
    sv[wid * 64 + 32 + lane] = v1;  si[wid * 64 + 32 + lane] = i1;
    __syncthreads();

    for (int j = 0; j < MAXK; ++j) {
        float bv = sv[wid * 64 + lane];      int bp = wid * 64 + lane;
        float ov = sv[wid * 64 + 32 + lane]; int op = wid * 64 + 32 + lane;
        if (ov > bv || (ov == bv && op < bp)) { bv = ov; bp = op; }
#pragma unroll
        for (int o = 16; o; o >>= 1) {
            float xv = __shfl_xor_sync(FULLMASK, bv, o);
            int   xp = __shfl_xor_sync(FULLMASK, bp, o);
            if (xv > bv || (xv == bv && xp < bp)) { bv = xv; bp = xp; }
        }
        if (lane == 0) { wv[wid] = bv; wp[wid] = bp; }
        __syncthreads();
        if (wid == 0) {
            float cv2 = wv[lane]; int cp2 = wp[lane];
#pragma unroll
            for (int o = 16; o; o >>= 1) {
                float xv = __shfl_xor_sync(FULLMASK, cv2, o);
                int   xp = __shfl_xor_sync(FULLMASK, cp2, o);
                if (xv > cv2 || (xv == cv2 && xp < cp2)) { cv2 = xv; cp2 = xp; }
            }
            if (lane == 0) {
                g_topv[row * MAXK + j] = cv2;
                g_topi[row * MAXK + j] = si[cp2];
                sv[cp2] = NEG_BIG;
            }
        }
        __syncthreads();
    }
}

// ---------------- kernel 5: softmax(top-kd) + gather + weighted sum ----------------
__global__ void k_aggregate(const float* __restrict__ P,
                            const int* __restrict__ kdyn,
                            float* __restrict__ out) {
    int row = blockIdx.x;
    int tid = threadIdx.x;
    __shared__ float ws[MAXK];
    __shared__ int   idx[MAXK];
    __shared__ float s_inv;

    int kd = *kdyn;
    kd = kd < 0 ? 0 : (kd > MAXK ? MAXK : kd);

    if (tid < MAXK) {
        float v = g_topv[row * MAXK + tid];
        idx[tid] = g_topi[row * MAXK + tid];
        float m = (kd > 0) ? g_topv[row * MAXK] : -1e9f;
        float mv = (tid < kd) ? v : -1e9f;
        ws[tid] = expf(mv - m);
    }
    __syncthreads();
    if (tid == 0) {
        float s = 0.f;
#pragma unroll
        for (int j = 0; j < MAXK; ++j) s += ws[j];
        s_inv = 1.0f / s;
    }
    __syncthreads();

    float a = 0.f;
#pragma unroll 4
    for (int j = 0; j < MAXK; ++j) {
        float w = ws[j];
        if (w != 0.f) a += w * P[(size_t)idx[j] * DIM + tid];
    }
    out[row * DIM + tid] = a * s_inv;
}

// ---------------- launcher ----------------
extern "C" void kernel_launch(void* const* d_in, const int* in_sizes, int n_in,
                              void* d_out, int out_size) {
    const float* hidden      = (const float*)d_in[0];
    const float* pool_params = (const float*)d_in[1];
    const float* pool_keys   = (const float*)d_in[2];
    const float* W           = (const float*)d_in[3];
    const float* bias        = (const float*)d_in[4];
    const int*   k_dynamic   = (const int*)d_in[5];
    float* out = (float*)d_out;

    int N = in_sizes[2] / DIM;

    static const size_t SMEM3 = (size_t)(BATCH * DIM + BN * KSTRIDE) * sizeof(float);
    cudaFuncSetAttribute(k_scores, cudaFuncAttributeMaxDynamicSharedMemorySize, (int)SMEM3);

    int segs = (N + SEGLEN - 1) / SEGLEN;
    if (segs > MAX_SEGS) segs = MAX_SEGS;  // safety (N <= 1M by scratch sizing)

    k_pool_partial<<<BATCH * 8, 256>>>(hidden);
    k_query<<<BATCH, DIM>>>(W, bias);
    int nblk = (N + BN - 1) / BN;
    k_scores<<<nblk, 256, SMEM3>>>(pool_keys, N);
    k_topk_part<<<BATCH * segs, 256>>>(N, segs);
    k_topk_merge<<<BATCH, 1024>>>(segs);
    k_aggregate<<<BATCH, DIM>>>(pool_params, k_dynamic, out);
}

// round 5
// speedup vs baseline: 1.7219x; 1.7219x over previous
#include <cuda_runtime.h>
#include <cuda_bf16.h>

// Problem constants (fixed by setup_inputs)
#define BATCH 32
#define TSEQ  1024
#define DIM   512
#define NMAX  500000
#define MAXK  64

#define FULLMASK 0xffffffffu
#define NEG_BIG (-3.0e38f)

#define NBINS 2048            // sign + 8 exp + 2 mantissa bits
#define SEGS2 8               // histogram/filter blocks per row
#define CAP   16384           // max candidates per row

// ---------------- device scratch (no allocations allowed) ----------------
__device__ float    g_part[BATCH * 8 * DIM];
__device__ float    g_query[BATCH * DIM];
__device__ float    g_scores[BATCH * NMAX];      // 64 MB (L2-resident)
__device__ unsigned g_hist[BATCH * NBINS];
__device__ unsigned g_thr[BATCH];
__device__ int      g_cnt[BATCH];
__device__ float    g_cv[BATCH * CAP];
__device__ int      g_ci[BATCH * CAP];
__device__ float    g_topv[BATCH * MAXK];
__device__ int      g_topi[BATCH * MAXK];

// monotone float->uint map: a > b  <=>  map(a) > map(b)
__device__ __forceinline__ unsigned fmap(float f) {
    unsigned u = __float_as_uint(f);
    return u ^ ((unsigned)((int)u >> 31) | 0x80000000u);
}

// ---------------- kernel 1: partial mean over T ----------------
__global__ void k_pool_partial(const float* __restrict__ hidden) {
    int b = blockIdx.x >> 3;
    int chunk = blockIdx.x & 7;
    int tid = threadIdx.x;
    const float* base = hidden + ((size_t)b * TSEQ + chunk * 128) * DIM;
    float a0 = 0.f, a1 = 0.f;
#pragma unroll 4
    for (int t = 0; t < 128; ++t) {
        a0 += base[t * DIM + tid];
        a1 += base[t * DIM + tid + 256];
    }
    g_part[(b * 8 + chunk) * DIM + tid]       = a0;
    g_part[(b * 8 + chunk) * DIM + tid + 256] = a1;
}

// ---------------- kernel 2: query = mean @ W + b ----------------
__global__ void k_query(const float* __restrict__ W, const float* __restrict__ bias) {
    int b = blockIdx.x;
    int j = threadIdx.x;
    __shared__ float sp[DIM];
    float s = 0.f;
#pragma unroll
    for (int c = 0; c < 8; ++c) s += g_part[(b * 8 + c) * DIM + j];
    sp[j] = s * (1.0f / (float)TSEQ);
    __syncthreads();
    float q = bias[j];
#pragma unroll 8
    for (int d = 0; d < DIM; ++d) q += sp[d] * W[d * DIM + j];
    g_query[b * DIM + j] = q;
}

// ---------------- kernel 3: scores (round-2 proven config: BN=256, 8x4 tile) ----------------
#define BN 256
#define BK 128
#define KSTRIDE (BK + 2)   // lane byte-stride 520 -> 520%128=8 -> conflict-free LDS.64 phases

__device__ __forceinline__ unsigned long long f32x2_fma(unsigned long long a,
                                                        unsigned long long b,
                                                        unsigned long long c) {
    unsigned long long d;
    asm("fma.rn.f32x2 %0, %1, %2, %3;" : "=l"(d) : "l"(a), "l"(b), "l"(c));
    return d;
}

__global__ void __launch_bounds__(256, 1)
k_scores(const float* __restrict__ keys, int N) {
    extern __shared__ float smem[];
    float* qs = smem;                 // [32][512]
    float* ks = smem + BATCH * DIM;   // [BN][KSTRIDE]

    int tid = threadIdx.x;
    int tx = tid & 63;
    int ty = tid >> 6;
    int n0 = blockIdx.x * BN;

#pragma unroll
    for (int i = 0; i < (BATCH * DIM) / 256; ++i)
        qs[tid + i * 256] = g_query[tid + i * 256];

    unsigned long long acc[8][4];
#pragma unroll
    for (int i = 0; i < 8; ++i)
#pragma unroll
        for (int j = 0; j < 4; ++j) acc[i][j] = 0ull;

    for (int kt = 0; kt < DIM / BK; ++kt) {
        __syncthreads();
#pragma unroll
        for (int it = 0; it < 32; ++it) {
            int f = tid + it * 256;
            int key = f >> 5;
            int kq = f & 31;
            int gk = n0 + key;
            float4 v;
            if (gk < N) {
                v = *reinterpret_cast<const float4*>(&keys[(size_t)gk * DIM + kt * BK + kq * 4]);
            } else {
                v = make_float4(0.f, 0.f, 0.f, 0.f);
            }
            float2* dst = reinterpret_cast<float2*>(&ks[key * KSTRIDE + kq * 4]);
            dst[0] = make_float2(v.x, v.y);
            dst[1] = make_float2(v.z, v.w);
        }
        __syncthreads();

#pragma unroll 4
        for (int kp = 0; kp < BK; kp += 2) {
            unsigned long long kv[4], qv[8];
#pragma unroll
            for (int j = 0; j < 4; ++j)
                kv[j] = *reinterpret_cast<const unsigned long long*>(&ks[(tx + j * 64) * KSTRIDE + kp]);
#pragma unroll
            for (int i = 0; i < 8; ++i)
                qv[i] = *reinterpret_cast<const unsigned long long*>(&qs[(ty * 8 + i) * DIM + kt * BK + kp]);
#pragma unroll
            for (int i = 0; i < 8; ++i)
#pragma unroll
                for (int j = 0; j < 4; ++j)
                    acc[i][j] = f32x2_fma(qv[i], kv[j], acc[i][j]);
        }
    }

    const float scale = 1.0f / sqrtf((float)DIM);
#pragma unroll
    for (int i = 0; i < 8; ++i) {
        int b = ty * 8 + i;
#pragma unroll
        for (int j = 0; j < 4; ++j) {
            int n = n0 + tx + j * 64;
            if (n < N) {
                unsigned long long u = acc[i][j];
                float lo = __uint_as_float((unsigned)(u & 0xffffffffull));
                float hi = __uint_as_float((unsigned)(u >> 32));
                g_scores[(size_t)b * N + n] = (lo + hi) * scale;
            }
        }
    }
}

// ---------------- kernel Z: zero histogram + counters ----------------
__global__ void k_zero() {
    int t = blockIdx.x * blockDim.x + threadIdx.x;
    if (t < BATCH * NBINS) g_hist[t] = 0u;
    if (t < BATCH) g_cnt[t] = 0;
}

// ---------------- kernel H: per-row 2048-bin histogram of mapped score bits ----------------
__global__ void __launch_bounds__(256)
k_hist(int N) {
    int row = blockIdx.x / SEGS2;
    int seg = blockIdx.x % SEGS2;
    int tid = threadIdx.x;

    __shared__ unsigned h[NBINS];
#pragma unroll
    for (int i = 0; i < NBINS / 256; ++i) h[tid + i * 256] = 0u;
    __syncthreads();

    int chunk = (((N + SEGS2 - 1) / SEGS2) + 3) & ~3;
    int s0 = seg * chunk;
    int s1 = s0 + chunk; if (s1 > N) s1 = N;
    const float* S = g_scores + (size_t)row * N;

    for (int i = s0 + (tid << 2); i < s1; i += 256 * 4) {
        if (i + 3 < s1) {
            float4 x = *reinterpret_cast<const float4*>(S + i);
            atomicAdd(&h[fmap(x.x) >> 21], 1u);
            atomicAdd(&h[fmap(x.y) >> 21], 1u);
            atomicAdd(&h[fmap(x.z) >> 21], 1u);
            atomicAdd(&h[fmap(x.w) >> 21], 1u);
        } else {
            for (int q = i; q < s1; ++q) atomicAdd(&h[fmap(S[q]) >> 21], 1u);
        }
    }
    __syncthreads();
#pragma unroll
    for (int i = 0; i < NBINS / 256; ++i) {
        unsigned c = h[tid + i * 256];
        if (c) atomicAdd(&g_hist[row * NBINS + tid + i * 256], c);
    }
}

// ---------------- kernel S: find threshold bin (64th largest) ----------------
__global__ void __launch_bounds__(256)
k_scan() {
    int row = blockIdx.x;
    int tid = threadIdx.x;
    __shared__ unsigned ps[256];
    // chunk t covers 8 bins in DESCENDING order: bins [NBINS-1-8t .. NBINS-8-8t]
    unsigned s = 0;
#pragma unroll
    for (int j = 0; j < 8; ++j) s += g_hist[row * NBINS + (NBINS - 1 - tid * 8 - j)];
    ps[tid] = s;
    __syncthreads();
    if (tid == 0) {
        unsigned cum = 0;
        int t = 0;
        for (; t < 256; ++t) {
            if (cum + ps[t] >= MAXK) break;
            cum += ps[t];
        }
        unsigned thr = 0;  // fallback: everything passes
        if (t < 256) {
            for (int j = 0; j < 8; ++j) {
                int b = NBINS - 1 - t * 8 - j;
                cum += g_hist[row * NBINS + b];
                if (cum >= MAXK) { thr = (unsigned)b << 21; break; }
            }
        }
        g_thr[row] = thr;
    }
}

// ---------------- kernel F: append candidates >= threshold ----------------
__global__ void __launch_bounds__(256)
k_filter(int N) {
    int row = blockIdx.x / SEGS2;
    int seg = blockIdx.x % SEGS2;
    int tid = threadIdx.x;
    unsigned thr = g_thr[row];

    int chunk = (((N + SEGS2 - 1) / SEGS2) + 3) & ~3;
    int s0 = seg * chunk;
    int s1 = s0 + chunk; if (s1 > N) s1 = N;
    const float* S = g_scores + (size_t)row * N;

    for (int i = s0 + (tid << 2); i < s1; i += 256 * 4) {
        float a[4];
        int m = (i + 3 < s1) ? 4 : (s1 - i);
        if (m == 4) {
            float4 x = *reinterpret_cast<const float4*>(S + i);
            a[0] = x.x; a[1] = x.y; a[2] = x.z; a[3] = x.w;
        } else {
            for (int q = 0; q < 4; ++q) a[q] = (q < m) ? S[i + q] : NEG_BIG;
        }
#pragma unroll
        for (int q = 0; q < 4; ++q) {
            if (q < m && fmap(a[q]) >= thr) {
                int pos = atomicAdd(&g_cnt[row], 1);
                if (pos < CAP) {
                    g_cv[row * CAP + pos] = a[q];
                    g_ci[row * CAP + pos] = i + q;
                }
            }
        }
    }
}

// ---------------- warp helpers for exact merge ----------------
__device__ __forceinline__ float warp_min32(float v) {
#pragma unroll
    for (int o = 16; o; o >>= 1) v = fminf(v, __shfl_xor_sync(FULLMASK, v, o));
    return v;
}

__device__ __forceinline__ void topk_insert4(float a0, float a1, float a2, float a3,
                                             int base, float& v0, float& v1,
                                             int& i0, int& i1, float& thr) {
    unsigned pm = (unsigned)(a0 > thr) | ((unsigned)(a1 > thr) << 1) |
                  ((unsigned)(a2 > thr) << 2) | ((unsigned)(a3 > thr) << 3);
    while (__any_sync(FULLMASK, pm != 0)) {
        int c = __ffs(pm) - 1;
        float cv = (c == 0) ? a0 : (c == 1) ? a1 : (c == 2) ? a2 : a3;
        int ci = base + c;
        unsigned ball = __ballot_sync(FULLMASK, pm != 0);
        int src = __ffs(ball) - 1;
        float cand = __shfl_sync(FULLMASK, cv, src);
        int candi = __shfl_sync(FULLMASK, ci, src);
        int lane = threadIdx.x & 31;
        if (lane == src) pm &= pm - 1;
        if (cand > thr) {
            float mn = fminf(v0, v1);
            float wmn = warp_min32(mn);
            unsigned who = __ballot_sync(FULLMASK, mn == wmn);
            int wl = __ffs(who) - 1;
            if (lane == wl) {
                if (v0 <= v1) { v0 = cand; i0 = candi; }
                else          { v1 = cand; i1 = candi; }
            }
            thr = warp_min32(fminf(v0, v1));
        }
        if (pm) {
            if ((pm & 1u) && a0 <= thr) pm &= ~1u;
            if ((pm & 2u) && a1 <= thr) pm &= ~2u;
            if ((pm & 4u) && a2 <= thr) pm &= ~4u;
            if ((pm & 8u) && a3 <= thr) pm &= ~8u;
        }
    }
}

// ---------------- kernel M: exact sorted top-64 from candidates ----------------
// grid = BATCH, 1024 threads. Tie-break: value desc, then index asc (matches lax.top_k).
__global__ void __launch_bounds__(1024)
k_topk_merge() {
    int row = blockIdx.x;
    int tid = threadIdx.x;
    int lane = tid & 31;
    int wid = tid >> 5;

    int C = g_cnt[row]; if (C > CAP) C = CAP;
    const float* CV = g_cv + (size_t)row * CAP;
    const int*   CI = g_ci + (size_t)row * CAP;

    float v0 = NEG_BIG, v1 = NEG_BIG;
    int i0 = 0, i1 = 0;
    float thr = NEG_BIG;

    int iters = (C + 4095) >> 12;
    for (int it = 0; it < iters; ++it) {
        int f = (it << 12) + (tid << 2);
        float a0 = (f + 0 < C) ? CV[f + 0] : NEG_BIG;
        float a1 = (f + 1 < C) ? CV[f + 1] : NEG_BIG;
        float a2 = (f + 2 < C) ? CV[f + 2] : NEG_BIG;
        float a3 = (f + 3 < C) ? CV[f + 3] : NEG_BIG;
        topk_insert4(a0, a1, a2, a3, f, v0, v1, i0, i1, thr);
    }
    // slot -> original index; also use original index for tie-break ordering
    i0 = (v0 > NEG_BIG) ? CI[i0] : 0x7fffffff;
    i1 = (v1 > NEG_BIG) ? CI[i1] : 0x7fffffff;

    __shared__ float sv[2048];
    __shared__ int   si[2048];
    __shared__ float wv[32];
    __shared__ int   wp[32];
    __shared__ int   wsrc[32];
    sv[wid * 64 + lane]      = v0;  si[wid * 64 + lane]      = i0;
    sv[wid * 64 + 32 + lane] = v1;  si[wid * 64 + 32 + lane] = i1;
    __syncthreads();

    for (int j = 0; j < MAXK; ++j) {
        // pick (max value, min original index) among remaining
        float bv = sv[wid * 64 + lane];      int bi = si[wid * 64 + lane];      int bp = wid * 64 + lane;
        float ov = sv[wid * 64 + 32 + lane]; int oi = si[wid * 64 + 32 + lane]; int op = wid * 64 + 32 + lane;
        if (ov > bv || (ov == bv && oi < bi)) { bv = ov; bi = oi; bp = op; }
#pragma unroll
        for (int o = 16; o; o >>= 1) {
            float xv = __shfl_xor_sync(FULLMASK, bv, o);
            int   xi = __shfl_xor_sync(FULLMASK, bi, o);
            int   xp = __shfl_xor_sync(FULLMASK, bp, o);
            if (xv > bv || (xv == bv && xi < bi)) { bv = xv; bi = xi; bp = xp; }
        }
        if (lane == 0) { wv[wid] = bv; wp[wid] = bi; wsrc[wid] = bp; }
        __syncthreads();
        if (wid == 0) {
            float cv2 = wv[lane]; int ci2 = wp[lane]; int cp2 = wsrc[lane];
#pragma unroll
            for (int o = 16; o; o >>= 1) {
                float xv = __shfl_xor_sync(FULLMASK, cv2, o);
                int   xi = __shfl_xor_sync(FULLMASK, ci2, o);
                int   xp = __shfl_xor_sync(FULLMASK, cp2, o);
                if (xv > cv2 || (xv == cv2 && xi < ci2)) { cv2 = xv; ci2 = xi; cp2 = xp; }
            }
            if (lane == 0) {
                g_topv[row * MAXK + j] = cv2;
                g_topi[row * MAXK + j] = ci2;
                sv[cp2] = NEG_BIG;
                si[cp2] = 0x7fffffff;
            }
        }
        __syncthreads();
    }
}

// ---------------- kernel 5: softmax(top-kd) + gather + weighted sum ----------------
__global__ void k_aggregate(const float* __restrict__ P,
                            const int* __restrict__ kdyn,
                            float* __restrict__ out) {
    int row = blockIdx.x;
    int tid = threadIdx.x;
    __shared__ float ws[MAXK];
    __shared__ int   idx[MAXK];
    __shared__ float s_inv;

    int kd = *kdyn;
    kd = kd < 0 ? 0 : (kd > MAXK ? MAXK : kd);

    if (tid < MAXK) {
        float v = g_topv[row * MAXK + tid];
        idx[tid] = g_topi[row * MAXK + tid];
        float m = (kd > 0) ? g_topv[row * MAXK] : -1e9f;
        float mv = (tid < kd) ? v : -1e9f;
        ws[tid] = expf(mv - m);
    }
    __syncthreads();
    if (tid == 0) {
        float s = 0.f;
#pragma unroll
        for (int j = 0; j < MAXK; ++j) s += ws[j];
        s_inv = 1.0f / s;
    }
    __syncthreads();

    float a = 0.f;
#pragma unroll 4
    for (int j = 0; j < MAXK; ++j) {
        float w = ws[j];
        if (w != 0.f) a += w * P[(size_t)idx[j] * DIM + tid];
    }
    out[row * DIM + tid] = a * s_inv;
}

// ---------------- launcher ----------------
extern "C" void kernel_launch(void* const* d_in, const int* in_sizes, int n_in,
                              void* d_out, int out_size) {
    const float* hidden      = (const float*)d_in[0];
    const float* pool_params = (const float*)d_in[1];
    const float* pool_keys   = (const float*)d_in[2];
    const float* W           = (const float*)d_in[3];
    const float* bias        = (const float*)d_in[4];
    const int*   k_dynamic   = (const int*)d_in[5];
    float* out = (float*)d_out;

    int N = in_sizes[2] / DIM;

    static const size_t SMEM3 = (size_t)(BATCH * DIM + BN * KSTRIDE) * sizeof(float);
    cudaFuncSetAttribute(k_scores, cudaFuncAttributeMaxDynamicSharedMemorySize, (int)SMEM3);

    k_pool_partial<<<BATCH * 8, 256>>>(hidden);
    k_query<<<BATCH, DIM>>>(W, bias);
    int nblk = (N + BN - 1) / BN;
    k_scores<<<nblk, 256, SMEM3>>>(pool_keys, N);
    k_zero<<<(BATCH * NBINS + 255) / 256, 256>>>();
    k_hist<<<BATCH * SEGS2, 256>>>(N);
    k_scan<<<BATCH, 256>>>();
    k_filter<<<BATCH * SEGS2, 256>>>(N);
    k_topk_merge<<<BATCH, 1024>>>();
    k_aggregate<<<BATCH, DIM>>>(pool_params, k_dynamic, out);
}

// round 7
// speedup vs baseline: 1.7837x; 1.0359x over previous
#include <cuda_runtime.h>
#include <cuda_bf16.h>

// Problem constants (fixed by setup_inputs)
#define BATCH 32
#define TSEQ  1024
#define DIM   512
#define NMAX  500000
#define MAXK  64

#define FULLMASK 0xffffffffu
#define NEG_BIG (-3.0e38f)

#define NBINS 2048
#define SEGS2 8
#define CAP   16384

// tensor-core scores tiling
#define TCN 256        // keys per block
#define KC  64         // k-chunk
#define KS  72         // key row stride in bf16 (144 B -> conflict-free frag loads)
#define QS  520        // query row stride in bf16 (1040 B -> conflict-free frag loads)

#define SCALE_D 0.044194173824159216f  // 1/sqrt(512)

// ---------------- device scratch (no allocations allowed) ----------------
__device__ float          g_part[BATCH * 8 * DIM];
__device__ float          g_query[BATCH * DIM];
__device__ unsigned short g_sbf[(size_t)BATCH * NMAX];   // approx scores, bf16 bits (32 MB)
__device__ unsigned       g_hist[BATCH * NBINS];
__device__ unsigned       g_thr[BATCH];
__device__ int            g_cnt[BATCH];
__device__ float          g_cv[BATCH * CAP];
__device__ int            g_ci[BATCH * CAP];
__device__ float          g_topv[BATCH * MAXK];
__device__ int            g_topi[BATCH * MAXK];

// monotone map on bf16 bit pattern: a > b (as floats) <=> map16(a) > map16(b)
__device__ __forceinline__ unsigned map16(unsigned u) {
    unsigned s = u >> 15;
    return (u ^ (0x8000u | (0x7FFFu & (0u - s)))) & 0xFFFFu;
}

// ---------------- kernel 1: partial mean over T ----------------
__global__ void k_pool_partial(const float* __restrict__ hidden) {
    int b = blockIdx.x >> 3;
    int chunk = blockIdx.x & 7;
    int tid = threadIdx.x;
    const float* base = hidden + ((size_t)b * TSEQ + chunk * 128) * DIM;
    float a0 = 0.f, a1 = 0.f;
#pragma unroll 4
    for (int t = 0; t < 128; ++t) {
        a0 += base[t * DIM + tid];
        a1 += base[t * DIM + tid + 256];
    }
    g_part[(b * 8 + chunk) * DIM + tid]       = a0;
    g_part[(b * 8 + chunk) * DIM + tid + 256] = a1;
}

// ---------------- kernel 2: query = mean @ W + b ----------------
__global__ void k_query(const float* __restrict__ W, const float* __restrict__ bias) {
    int b = blockIdx.x;
    int j = threadIdx.x;
    __shared__ float sp[DIM];
    float s = 0.f;
#pragma unroll
    for (int c = 0; c < 8; ++c) s += g_part[(b * 8 + c) * DIM + j];
    sp[j] = s * (1.0f / (float)TSEQ);
    __syncthreads();
    float q = bias[j];
#pragma unroll 8
    for (int d = 0; d < DIM; ++d) q += sp[d] * W[d * DIM + j];
    g_query[b * DIM + j] = q;
}

// ---------------- mma.sync m16n8k16 bf16 wrapper ----------------
__device__ __forceinline__ void mma_bf16(float c[4],
                                         unsigned a0, unsigned a1, unsigned a2, unsigned a3,
                                         unsigned b0, unsigned b1) {
    asm volatile(
        "mma.sync.aligned.m16n8k16.row.col.f32.bf16.bf16.f32 "
        "{%0,%1,%2,%3}, {%4,%5,%6,%7}, {%8,%9}, {%0,%1,%2,%3};"
        : "+f"(c[0]), "+f"(c[1]), "+f"(c[2]), "+f"(c[3])
        : "r"(a0), "r"(a1), "r"(a2), "r"(a3), "r"(b0), "r"(b1));
}

__device__ __forceinline__ unsigned pack_bf16x2(float lo, float hi) {
    __nv_bfloat162 p = __floats2bfloat162_rn(lo, hi);
    return *reinterpret_cast<unsigned*>(&p);
}

// ---------------- kernel 3: approx scores via tensor cores ----------------
// Block: 256 threads = 8 warps. Block tile: 32 batches x TCN keys.
// Warp w: keys [w*32, w*32+32): 2 m-tiles (batches) x 4 n-tiles (keys).
__global__ void __launch_bounds__(256, 2)
k_scores_tc(const float* __restrict__ keys, int N) {
    extern __shared__ __nv_bfloat16 sm[];
    __nv_bfloat16* qs = sm;              // [32][QS]
    __nv_bfloat16* ks = sm + BATCH * QS; // [TCN][KS]

    int tid = threadIdx.x;
    int w = tid >> 5, lane = tid & 31;
    int g = lane >> 2, tig = lane & 3;
    int n0 = blockIdx.x * TCN;

    // load queries fp32 -> bf16 smem (4096 float4 / 256 threads = 16 each)
#pragma unroll
    for (int it = 0; it < 16; ++it) {
        int f = tid + it * 256;
        int row = f >> 7;          // 128 float4 per row
        int kq = f & 127;
        float4 v = *reinterpret_cast<const float4*>(&g_query[row * DIM + kq * 4]);
        unsigned p0 = pack_bf16x2(v.x, v.y);
        unsigned p1 = pack_bf16x2(v.z, v.w);
        unsigned long long pk = ((unsigned long long)p1 << 32) | p0;
        *reinterpret_cast<unsigned long long*>(&qs[row * QS + kq * 4]) = pk;
    }

    float acc[2][4][4];
#pragma unroll
    for (int mt = 0; mt < 2; ++mt)
#pragma unroll
        for (int nt = 0; nt < 4; ++nt)
#pragma unroll
            for (int r = 0; r < 4; ++r) acc[mt][nt][r] = 0.f;

    for (int kt = 0; kt < DIM / KC; ++kt) {
        __syncthreads();
        // load key chunk: TCN keys x KC floats = 4096 float4, convert to bf16
#pragma unroll
        for (int it = 0; it < 16; ++it) {
            int f = tid + it * 256;
            int key = f >> 4;      // KC/4 = 16 float4 per key
            int kq = f & 15;
            int gk = n0 + key;
            float4 v = make_float4(0.f, 0.f, 0.f, 0.f);
            if (gk < N)
                v = *reinterpret_cast<const float4*>(&keys[(size_t)gk * DIM + kt * KC + kq * 4]);
            unsigned p0 = pack_bf16x2(v.x, v.y);
            unsigned p1 = pack_bf16x2(v.z, v.w);
            unsigned long long pk = ((unsigned long long)p1 << 32) | p0;
            *reinterpret_cast<unsigned long long*>(&ks[key * KS + kq * 4]) = pk;
        }
        __syncthreads();

#pragma unroll
        for (int s = 0; s < KC / 16; ++s) {
            int k0 = s * 16;
            // A fragments (queries), 2 m-tiles
            unsigned a[2][4];
#pragma unroll
            for (int mt = 0; mt < 2; ++mt) {
                const __nv_bfloat16* alo = &qs[(mt * 16 + g) * QS + kt * KC + k0 + tig * 2];
                const __nv_bfloat16* ahi = alo + 8 * QS;
                a[mt][0] = *reinterpret_cast<const unsigned*>(alo);
                a[mt][1] = *reinterpret_cast<const unsigned*>(ahi);
                a[mt][2] = *reinterpret_cast<const unsigned*>(alo + 8);
                a[mt][3] = *reinterpret_cast<const unsigned*>(ahi + 8);
            }
#pragma unroll
            for (int nt = 0; nt < 4; ++nt) {
                const __nv_bfloat16* bp = &ks[(w * 32 + nt * 8 + g) * KS + k0 + tig * 2];
                unsigned b0 = *reinterpret_cast<const unsigned*>(bp);
                unsigned b1 = *reinterpret_cast<const unsigned*>(bp + 8);
                mma_bf16(acc[0][nt], a[0][0], a[0][1], a[0][2], a[0][3], b0, b1);
                mma_bf16(acc[1][nt], a[1][0], a[1][1], a[1][2], a[1][3], b0, b1);
            }
        }
    }

    // epilogue: store bf16 approx scores
#pragma unroll
    for (int mt = 0; mt < 2; ++mt) {
#pragma unroll
        for (int nt = 0; nt < 4; ++nt) {
            int row_lo = mt * 16 + g;
            int row_hi = row_lo + 8;
            int col = n0 + w * 32 + nt * 8 + tig * 2;
            if (col < N) {   // col even, N even -> col+1 < N
                unsigned plo = pack_bf16x2(acc[mt][nt][0] * SCALE_D, acc[mt][nt][1] * SCALE_D);
                unsigned phi = pack_bf16x2(acc[mt][nt][2] * SCALE_D, acc[mt][nt][3] * SCALE_D);
                *reinterpret_cast<unsigned*>(&g_sbf[(size_t)row_lo * N + col]) = plo;
                *reinterpret_cast<unsigned*>(&g_sbf[(size_t)row_hi * N + col]) = phi;
            }
        }
    }
}

// ---------------- kernel Z: zero histogram + counters ----------------
__global__ void k_zero() {
    int t = blockIdx.x * blockDim.x + threadIdx.x;
    if (t < BATCH * NBINS) g_hist[t] = 0u;
    if (t < BATCH) g_cnt[t] = 0;
}

// ---------------- kernel H: per-row histogram of mapped bf16 bits ----------------
__global__ void __launch_bounds__(256)
k_hist(int N) {
    int row = blockIdx.x / SEGS2;
    int seg = blockIdx.x % SEGS2;
    int tid = threadIdx.x;

    __shared__ unsigned h[NBINS];
#pragma unroll
    for (int i = 0; i < NBINS / 256; ++i) h[tid + i * 256] = 0u;
    __syncthreads();

    int chunk = (((N + SEGS2 - 1) / SEGS2) + 7) & ~7;
    int s0 = seg * chunk;
    int s1 = s0 + chunk; if (s1 > N) s1 = N;
    const unsigned short* S = g_sbf + (size_t)row * N;

    for (int i = s0 + tid * 8; i < s1; i += 256 * 8) {
        if (i + 7 < s1) {
            uint4 x = *reinterpret_cast<const uint4*>(S + i);
            unsigned v[4] = {x.x, x.y, x.z, x.w};
#pragma unroll
            for (int q = 0; q < 4; ++q) {
                atomicAdd(&h[map16(v[q] & 0xFFFFu) >> 5], 1u);
                atomicAdd(&h[map16(v[q] >> 16) >> 5], 1u);
            }
        } else {
            for (int q = i; q < s1; ++q) atomicAdd(&h[map16(S[q]) >> 5], 1u);
        }
    }
    __syncthreads();
#pragma unroll
    for (int i = 0; i < NBINS / 256; ++i) {
        unsigned c = h[tid + i * 256];
        if (c) atomicAdd(&g_hist[row * NBINS + tid + i * 256], c);
    }
}

// ---------------- kernel S: threshold bin (rank-64), lowered one bin for bf16 error ----------------
__global__ void __launch_bounds__(256)
k_scan() {
    int row = blockIdx.x;
    int tid = threadIdx.x;
    __shared__ unsigned ps[256];
    unsigned s = 0;
#pragma unroll
    for (int j = 0; j < 8; ++j) s += g_hist[row * NBINS + (NBINS - 1 - tid * 8 - j)];
    ps[tid] = s;
    __syncthreads();
    if (tid == 0) {
        unsigned cum = 0;
        int t = 0;
        for (; t < 256; ++t) {
            if (cum + ps[t] >= MAXK) break;
            cum += ps[t];
        }
        unsigned thr = 0;
        if (t < 256) {
            for (int j = 0; j < 8; ++j) {
                int b = NBINS - 1 - t * 8 - j;
                cum += g_hist[row * NBINS + b];
                if (cum >= MAXK) {
                    int bm = (b > 0) ? (b - 1) : 0;  // one-bin safety margin
                    thr = (unsigned)bm << 5;
                    break;
                }
            }
        }
        g_thr[row] = thr;
    }
}

// ---------------- kernel F: collect candidate indices >= threshold ----------------
__global__ void __launch_bounds__(256)
k_filter(int N) {
    int row = blockIdx.x / SEGS2;
    int seg = blockIdx.x % SEGS2;
    int tid = threadIdx.x;
    unsigned thr = g_thr[row];

    int chunk = (((N + SEGS2 - 1) / SEGS2) + 7) & ~7;
    int s0 = seg * chunk;
    int s1 = s0 + chunk; if (s1 > N) s1 = N;
    const unsigned short* S = g_sbf + (size_t)row * N;

    for (int i = s0 + tid * 8; i < s1; i += 256 * 8) {
        if (i + 7 < s1) {
            uint4 x = *reinterpret_cast<const uint4*>(S + i);
            unsigned v[4] = {x.x, x.y, x.z, x.w};
#pragma unroll
            for (int q = 0; q < 4; ++q) {
                if (map16(v[q] & 0xFFFFu) >= thr) {
                    int pos = atomicAdd(&g_cnt[row], 1);
                    if (pos < CAP) g_ci[row * CAP + pos] = i + q * 2;
                }
                if (map16(v[q] >> 16) >= thr) {
                    int pos = atomicAdd(&g_cnt[row], 1);
                    if (pos < CAP) g_ci[row * CAP + pos] = i + q * 2 + 1;
                }
            }
        } else {
            for (int q = i; q < s1; ++q) {
                if (map16(S[q]) >= thr) {
                    int pos = atomicAdd(&g_cnt[row], 1);
                    if (pos < CAP) g_ci[row * CAP + pos] = q;
                }
            }
        }
    }
}

// ---------------- kernel R: exact fp32 rescore of candidates ----------------
// grid = BATCH, 256 threads = 8 warps, one warp per candidate.
__global__ void __launch_bounds__(256)
k_rescore(const float* __restrict__ keys) {
    int row = blockIdx.x;
    int w = threadIdx.x >> 5, lane = threadIdx.x & 31;
    int cnt = g_cnt[row]; if (cnt > CAP) cnt = CAP;
    const float* q = g_query + row * DIM;

    for (int c = w; c < cnt; c += 8) {
        int idx = g_ci[row * CAP + c];
        const float* kp = keys + (size_t)idx * DIM;
        float s = 0.f;
#pragma unroll
        for (int j = 0; j < 4; ++j) {
            float4 kv = *reinterpret_cast<const float4*>(kp + lane * 16 + j * 4);
            float4 qv = *reinterpret_cast<const float4*>(q + lane * 16 + j * 4);
            s += kv.x * qv.x + kv.y * qv.y + kv.z * qv.z + kv.w * qv.w;
        }
#pragma unroll
        for (int o = 16; o; o >>= 1) s += __shfl_xor_sync(FULLMASK, s, o);
        if (lane == 0) g_cv[row * CAP + c] = s * SCALE_D;
    }
}

// ---------------- warp helpers for exact merge ----------------
__device__ __forceinline__ float warp_min32(float v) {
#pragma unroll
    for (int o = 16; o; o >>= 1) v = fminf(v, __shfl_xor_sync(FULLMASK, v, o));
    return v;
}

__device__ __forceinline__ void topk_insert4(float a0, float a1, float a2, float a3,
                                             int base, float& v0, float& v1,
                                             int& i0, int& i1, float& thr) {
    unsigned pm = (unsigned)(a0 > thr) | ((unsigned)(a1 > thr) << 1) |
                  ((unsigned)(a2 > thr) << 2) | ((unsigned)(a3 > thr) << 3);
    while (__any_sync(FULLMASK, pm != 0)) {
        int c = __ffs(pm) - 1;
        float cv = (c == 0) ? a0 : (c == 1) ? a1 : (c == 2) ? a2 : a3;
        int ci = base + c;
        unsigned ball = __ballot_sync(FULLMASK, pm != 0);
        int src = __ffs(ball) - 1;
        float cand = __shfl_sync(FULLMASK, cv, src);
        int candi = __shfl_sync(FULLMASK, ci, src);
        int lane = threadIdx.x & 31;
        if (lane == src) pm &= pm - 1;
        if (cand > thr) {
            float mn = fminf(v0, v1);
            float wmn = warp_min32(mn);
            unsigned who = __ballot_sync(FULLMASK, mn == wmn);
            int wl = __ffs(who) - 1;
            if (lane == wl) {
                if (v0 <= v1) { v0 = cand; i0 = candi; }
                else          { v1 = cand; i1 = candi; }
            }
            thr = warp_min32(fminf(v0, v1));
        }
        if (pm) {
            if ((pm & 1u) && a0 <= thr) pm &= ~1u;
            if ((pm & 2u) && a1 <= thr) pm &= ~2u;
            if ((pm & 4u) && a2 <= thr) pm &= ~4u;
            if ((pm & 8u) && a3 <= thr) pm &= ~8u;
        }
    }
}

// ---------------- kernel M: exact sorted top-64 from candidates ----------------
__global__ void __launch_bounds__(1024)
k_topk_merge() {
    int row = blockIdx.x;
    int tid = threadIdx.x;
    int lane = tid & 31;
    int wid = tid >> 5;

    int C = g_cnt[row]; if (C > CAP) C = CAP;
    const float* CV = g_cv + (size_t)row * CAP;
    const int*   CI = g_ci + (size_t)row * CAP;

    float v0 = NEG_BIG, v1 = NEG_BIG;
    int i0 = 0, i1 = 0;
    float thr = NEG_BIG;

    int iters = (C + 4095) >> 12;
    for (int it = 0; it < iters; ++it) {
        int f = (it << 12) + (tid << 2);
        float a0 = (f + 0 < C) ? CV[f + 0] : NEG_BIG;
        float a1 = (f + 1 < C) ? CV[f + 1] : NEG_BIG;
        float a2 = (f + 2 < C) ? CV[f + 2] : NEG_BIG;
        float a3 = (f + 3 < C) ? CV[f + 3] : NEG_BIG;
        topk_insert4(a0, a1, a2, a3, f, v0, v1, i0, i1, thr);
    }
    i0 = (v0 > NEG_BIG) ? CI[i0] : 0x7fffffff;
    i1 = (v1 > NEG_BIG) ? CI[i1] : 0x7fffffff;

    __shared__ float sv[2048];
    __shared__ int   si[2048];
    __shared__ float wv[32];
    __shared__ int   wp[32];
    __shared__ int   wsrc[32];
    sv[wid * 64 + lane]      = v0;  si[wid * 64 + lane]      = i0;
    sv[wid * 64 + 32 + lane] = v1;  si[wid * 64 + 32 + lane] = i1;
    __syncthreads();

    for (int j = 0; j < MAXK; ++j) {
        float bv = sv[wid * 64 + lane];      int bi = si[wid * 64 + lane];      int bp = wid * 64 + lane;
        float ov = sv[wid * 64 + 32 + lane]; int oi = si[wid * 64 + 32 + lane]; int op = wid * 64 + 32 + lane;
        if (ov > bv || (ov == bv && oi < bi)) { bv = ov; bi = oi; bp = op; }
#pragma unroll
        for (int o = 16; o; o >>= 1) {
            float xv = __shfl_xor_sync(FULLMASK, bv, o);
            int   xi = __shfl_xor_sync(FULLMASK, bi, o);
            int   xp = __shfl_xor_sync(FULLMASK, bp, o);
            if (xv > bv || (xv == bv && xi < bi)) { bv = xv; bi = xi; bp = xp; }
        }
        if (lane == 0) { wv[wid] = bv; wp[wid] = bi; wsrc[wid] = bp; }
        __syncthreads();
        if (wid == 0) {
            float cv2 = wv[lane]; int ci2 = wp[lane]; int cp2 = wsrc[lane];
#pragma unroll
            for (int o = 16; o; o >>= 1) {
                float xv = __shfl_xor_sync(FULLMASK, cv2, o);
                int   xi = __shfl_xor_sync(FULLMASK, ci2, o);
                int   xp = __shfl_xor_sync(FULLMASK, cp2, o);
                if (xv > cv2 || (xv == cv2 && xi < ci2)) { cv2 = xv; ci2 = xi; cp2 = xp; }
            }
            if (lane == 0) {
                g_topv[row * MAXK + j] = cv2;
                g_topi[row * MAXK + j] = ci2;
                sv[cp2] = NEG_BIG;
                si[cp2] = 0x7fffffff;
            }
        }
        __syncthreads();
    }
}

// ---------------- kernel 5: softmax(top-kd) + gather + weighted sum ----------------
__global__ void k_aggregate(const float* __restrict__ P,
                            const int* __restrict__ kdyn,
                            float* __restrict__ out) {
    int row = blockIdx.x;
    int tid = threadIdx.x;
    __shared__ float ws[MAXK];
    __shared__ int   idx[MAXK];
    __shared__ float s_inv;

    int kd = *kdyn;
    kd = kd < 0 ? 0 : (kd > MAXK ? MAXK : kd);

    if (tid < MAXK) {
        float v = g_topv[row * MAXK + tid];
        idx[tid] = g_topi[row * MAXK + tid];
        float m = (kd > 0) ? g_topv[row * MAXK] : -1e9f;
        float mv = (tid < kd) ? v : -1e9f;
        ws[tid] = expf(mv - m);
    }
    __syncthreads();
    if (tid == 0) {
        float s = 0.f;
#pragma unroll
        for (int j = 0; j < MAXK; ++j) s += ws[j];
        s_inv = 1.0f / s;
    }
    __syncthreads();

    float a = 0.f;
#pragma unroll 4
    for (int j = 0; j < MAXK; ++j) {
        float w = ws[j];
        if (w != 0.f) a += w * P[(size_t)idx[j] * DIM + tid];
    }
    out[row * DIM + tid] = a * s_inv;
}

// ---------------- launcher ----------------
extern "C" void kernel_launch(void* const* d_in, const int* in_sizes, int n_in,
                              void* d_out, int out_size) {
    const float* hidden      = (const float*)d_in[0];
    const float* pool_params = (const float*)d_in[1];
    const float* pool_keys   = (const float*)d_in[2];
    const float* W           = (const float*)d_in[3];
    const float* bias        = (const float*)d_in[4];
    const int*   k_dynamic   = (const int*)d_in[5];
    float* out = (float*)d_out;

    int N = in_sizes[2] / DIM;

    static const size_t SMEMTC = (size_t)(BATCH * QS + TCN * KS) * sizeof(__nv_bfloat16);
    cudaFuncSetAttribute(k_scores_tc, cudaFuncAttributeMaxDynamicSharedMemorySize, (int)SMEMTC);

    k_pool_partial<<<BATCH * 8, 256>>>(hidden);
    k_query<<<BATCH, DIM>>>(W, bias);
    k_zero<<<(BATCH * NBINS + 255) / 256, 256>>>();
    int nblk = (N + TCN - 1) / TCN;
    k_scores_tc<<<nblk, 256, SMEMTC>>>(pool_keys, N);
    k_hist<<<BATCH * SEGS2, 256>>>(N);
    k_scan<<<BATCH, 256>>>();
    k_filter<<<BATCH * SEGS2, 256>>>(N);
    k_rescore<<<BATCH, 256>>>(pool_keys);
    k_topk_merge<<<BATCH, 1024>>>();
    k_aggregate<<<BATCH, DIM>>>(pool_params, k_dynamic, out);
}

// round 9
// speedup vs baseline: 1.7848x; 1.0006x over previous
#include <cuda_runtime.h>
#include <cuda_bf16.h>

// Problem constants (fixed by setup_inputs)
#define BATCH 32
#define TSEQ  1024
#define DIM   512
#define NMAX  500000
#define MAXK  64

#define FULLMASK 0xffffffffu
#define NEG_BIG (-3.0e38f)

#define SEGS2 16
#define RSEG  32
#define CAP   16384
#define MAXBLK 2048

// tensor-core scores tiling
#define TCN 256        // keys per block
#define KC  64         // k-chunk
#define KS  72         // key row stride in bf16
#define QS  520        // query row stride in bf16

#define SCALE_D 0.044194173824159216f  // 1/sqrt(512)

// ---------------- device scratch (no allocations allowed) ----------------
__device__ float          g_part[BATCH * 8 * DIM];
__device__ float          g_query[BATCH * DIM];
__device__ unsigned short g_sbf[(size_t)BATCH * NMAX];   // approx scores, bf16 bits (32 MB)
__device__ unsigned       g_bmax[BATCH * MAXBLK];        // per-(row, score-block) max (mapped u16)
__device__ unsigned       g_thr[BATCH];
__device__ int            g_cnt[BATCH];
__device__ float          g_cv[BATCH * CAP];
__device__ int            g_ci[BATCH * CAP];
__device__ float          g_topv[BATCH * MAXK];
__device__ int            g_topi[BATCH * MAXK];

// monotone map on bf16 bit pattern: a > b (as floats) <=> map16(a) > map16(b)
__device__ __forceinline__ unsigned map16(unsigned u) {
    unsigned s = u >> 15;
    return (u ^ (0x8000u | (0x7FFFu & (0u - s)))) & 0xFFFFu;
}

// ---------------- kernel 1: partial mean over T ----------------
__global__ void k_pool_partial(const float* __restrict__ hidden) {
    int b = blockIdx.x >> 3;
    int chunk = blockIdx.x & 7;
    int tid = threadIdx.x;
    const float* base = hidden + ((size_t)b * TSEQ + chunk * 128) * DIM;
    float a0 = 0.f, a1 = 0.f;
#pragma unroll 4
    for (int t = 0; t < 128; ++t) {
        a0 += base[t * DIM + tid];
        a1 += base[t * DIM + tid + 256];
    }
    g_part[(b * 8 + chunk) * DIM + tid]       = a0;
    g_part[(b * 8 + chunk) * DIM + tid + 256] = a1;
}

// ---------------- kernel 2: query = mean @ W + b ----------------
__global__ void k_query(const float* __restrict__ W, const float* __restrict__ bias) {
    int b = blockIdx.x;
    int j = threadIdx.x;
    __shared__ float sp[DIM];
    float s = 0.f;
#pragma unroll
    for (int c = 0; c < 8; ++c) s += g_part[(b * 8 + c) * DIM + j];
    sp[j] = s * (1.0f / (float)TSEQ);
    __syncthreads();
    float q = bias[j];
#pragma unroll 8
    for (int d = 0; d < DIM; ++d) q += sp[d] * W[d * DIM + j];
    g_query[b * DIM + j] = q;
}

// ---------------- mma.sync m16n8k16 bf16 wrapper ----------------
__device__ __forceinline__ void mma_bf16(float c[4],
                                         unsigned a0, unsigned a1, unsigned a2, unsigned a3,
                                         unsigned b0, unsigned b1) {
    asm volatile(
        "mma.sync.aligned.m16n8k16.row.col.f32.bf16.bf16.f32 "
        "{%0,%1,%2,%3}, {%4,%5,%6,%7}, {%8,%9}, {%0,%1,%2,%3};"
        : "+f"(c[0]), "+f"(c[1]), "+f"(c[2]), "+f"(c[3])
        : "r"(a0), "r"(a1), "r"(a2), "r"(a3), "r"(b0), "r"(b1));
}

__device__ __forceinline__ unsigned pack_bf16x2(float lo, float hi) {
    __nv_bfloat162 p = __floats2bfloat162_rn(lo, hi);
    return *reinterpret_cast<unsigned*>(&p);
}

// ---------------- kernel 3: approx scores via tensor cores + per-tile row max ----------------
__global__ void __launch_bounds__(256, 2)
k_scores_tc(const float* __restrict__ keys, int N) {
    extern __shared__ __nv_bfloat16 sm[];
    __nv_bfloat16* qs = sm;              // [32][QS]
    __nv_bfloat16* ks = sm + BATCH * QS; // [TCN][KS]
    __shared__ unsigned srmax[BATCH];

    int tid = threadIdx.x;
    int w = tid >> 5, lane = tid & 31;
    int g = lane >> 2, tig = lane & 3;
    int n0 = blockIdx.x * TCN;

    if (tid < BATCH) srmax[tid] = 0u;

    // load queries fp32 -> bf16 smem
#pragma unroll
    for (int it = 0; it < 16; ++it) {
        int f = tid + it * 256;
        int row = f >> 7;
        int kq = f & 127;
        float4 v = *reinterpret_cast<const float4*>(&g_query[row * DIM + kq * 4]);
        unsigned p0 = pack_bf16x2(v.x, v.y);
        unsigned p1 = pack_bf16x2(v.z, v.w);
        unsigned long long pk = ((unsigned long long)p1 << 32) | p0;
        *reinterpret_cast<unsigned long long*>(&qs[row * QS + kq * 4]) = pk;
    }

    float acc[2][4][4];
#pragma unroll
    for (int mt = 0; mt < 2; ++mt)
#pragma unroll
        for (int nt = 0; nt < 4; ++nt)
#pragma unroll
            for (int r = 0; r < 4; ++r) acc[mt][nt][r] = 0.f;

    for (int kt = 0; kt < DIM / KC; ++kt) {
        __syncthreads();
#pragma unroll
        for (int it = 0; it < 16; ++it) {
            int f = tid + it * 256;
            int key = f >> 4;
            int kq = f & 15;
            int gk = n0 + key;
            float4 v = make_float4(0.f, 0.f, 0.f, 0.f);
            if (gk < N)
                v = *reinterpret_cast<const float4*>(&keys[(size_t)gk * DIM + kt * KC + kq * 4]);
            unsigned p0 = pack_bf16x2(v.x, v.y);
            unsigned p1 = pack_bf16x2(v.z, v.w);
            unsigned long long pk = ((unsigned long long)p1 << 32) | p0;
            *reinterpret_cast<unsigned long long*>(&ks[key * KS + kq * 4]) = pk;
        }
        __syncthreads();

#pragma unroll
        for (int s = 0; s < KC / 16; ++s) {
            int k0 = s * 16;
            unsigned a[2][4];
#pragma unroll
            for (int mt = 0; mt < 2; ++mt) {
                const __nv_bfloat16* alo = &qs[(mt * 16 + g) * QS + kt * KC + k0 + tig * 2];
                const __nv_bfloat16* ahi = alo + 8 * QS;
                a[mt][0] = *reinterpret_cast<const unsigned*>(alo);
                a[mt][1] = *reinterpret_cast<const unsigned*>(ahi);
                a[mt][2] = *reinterpret_cast<const unsigned*>(alo + 8);
                a[mt][3] = *reinterpret_cast<const unsigned*>(ahi + 8);
            }
#pragma unroll
            for (int nt = 0; nt < 4; ++nt) {
                const __nv_bfloat16* bp = &ks[(w * 32 + nt * 8 + g) * KS + k0 + tig * 2];
                unsigned b0 = *reinterpret_cast<const unsigned*>(bp);
                unsigned b1 = *reinterpret_cast<const unsigned*>(bp + 8);
                mma_bf16(acc[0][nt], a[0][0], a[0][1], a[0][2], a[0][3], b0, b1);
                mma_bf16(acc[1][nt], a[1][0], a[1][1], a[1][2], a[1][3], b0, b1);
            }
        }
    }

    // epilogue: store bf16 scores + accumulate per-row tile max (valid cols only)
    unsigned mlo[2] = {0u, 0u}, mhi[2] = {0u, 0u};
#pragma unroll
    for (int mt = 0; mt < 2; ++mt) {
#pragma unroll
        for (int nt = 0; nt < 4; ++nt) {
            int row_lo = mt * 16 + g;
            int row_hi = row_lo + 8;
            int col = n0 + w * 32 + nt * 8 + tig * 2;
            if (col < N) {
                unsigned plo = pack_bf16x2(acc[mt][nt][0] * SCALE_D, acc[mt][nt][1] * SCALE_D);
                unsigned phi = pack_bf16x2(acc[mt][nt][2] * SCALE_D, acc[mt][nt][3] * SCALE_D);
                *reinterpret_cast<unsigned*>(&g_sbf[(size_t)row_lo * N + col]) = plo;
                *reinterpret_cast<unsigned*>(&g_sbf[(size_t)row_hi * N + col]) = phi;
                unsigned u;
                u = map16(plo & 0xFFFFu); if (u > mlo[mt]) mlo[mt] = u;
                u = map16(plo >> 16);     if (u > mlo[mt]) mlo[mt] = u;
                u = map16(phi & 0xFFFFu); if (u > mhi[mt]) mhi[mt] = u;
                u = map16(phi >> 16);     if (u > mhi[mt]) mhi[mt] = u;
            }
        }
    }
    __syncthreads();
#pragma unroll
    for (int mt = 0; mt < 2; ++mt) {
        atomicMax(&srmax[mt * 16 + g], mlo[mt]);
        atomicMax(&srmax[mt * 16 + 8 + g], mhi[mt]);
    }
    __syncthreads();
    if (tid < BATCH) g_bmax[tid * MAXBLK + blockIdx.x] = srmax[tid];
}

// ---------------- kernel RM: per-row max -> conservative threshold; zero counters ----------------
__global__ void __launch_bounds__(256)
k_rowmax(int nblk) {
    int row = blockIdx.x;
    int tid = threadIdx.x;
    __shared__ unsigned sm[256];
    unsigned m = 0u;
    for (int i = tid; i < nblk; i += 256) {
        unsigned v = g_bmax[row * MAXBLK + i];
        if (v > m) m = v;
    }
    sm[tid] = m;
    __syncthreads();
    for (int o = 128; o; o >>= 1) {
        if (tid < o) { if (sm[tid + o] > sm[tid]) sm[tid] = sm[tid + o]; }
        __syncthreads();
    }
    if (tid == 0) {
        unsigned maxbin = sm[0] >> 5;           // quarter-octave bins
        unsigned tb = (maxbin > 4u) ? (maxbin - 4u) : 0u;  // threshold = max/2 (4 quarter-octave bins)
        g_thr[row] = tb << 5;
        g_cnt[row] = 0;
    }
}

// ---------------- kernel F: collect candidate indices >= threshold ----------------
__global__ void __launch_bounds__(256)
k_filter(int N) {
    int row = blockIdx.x / SEGS2;
    int seg = blockIdx.x % SEGS2;
    int tid = threadIdx.x;
    unsigned thr = g_thr[row];

    int chunk = (((N + SEGS2 - 1) / SEGS2) + 7) & ~7;
    int s0 = seg * chunk;
    int s1 = s0 + chunk; if (s1 > N) s1 = N;
    const unsigned short* S = g_sbf + (size_t)row * N;

    for (int i = s0 + tid * 8; i < s1; i += 256 * 8) {
        if (i + 7 < s1) {
            uint4 x = *reinterpret_cast<const uint4*>(S + i);
            unsigned v[4] = {x.x, x.y, x.z, x.w};
#pragma unroll
            for (int q = 0; q < 4; ++q) {
                if (map16(v[q] & 0xFFFFu) >= thr) {
                    int pos = atomicAdd(&g_cnt[row], 1);
                    if (pos < CAP) g_ci[row * CAP + pos] = i + q * 2;
                }
                if (map16(v[q] >> 16) >= thr) {
                    int pos = atomicAdd(&g_cnt[row], 1);
                    if (pos < CAP) g_ci[row * CAP + pos] = i + q * 2 + 1;
                }
            }
        } else {
            for (int q = i; q < s1; ++q) {
                if (map16(S[q]) >= thr) {
                    int pos = atomicAdd(&g_cnt[row], 1);
                    if (pos < CAP) g_ci[row * CAP + pos] = q;
                }
            }
        }
    }
}

// ---------------- kernel R: exact fp32 rescore of candidates ----------------
// grid = BATCH * RSEG blocks, 256 threads, one warp per candidate (strided).
__global__ void __launch_bounds__(256)
k_rescore(const float* __restrict__ keys) {
    int row = blockIdx.x / RSEG;
    int seg = blockIdx.x % RSEG;
    int w = threadIdx.x >> 5, lane = threadIdx.x & 31;
    int cnt = g_cnt[row]; if (cnt > CAP) cnt = CAP;
    const float* q = g_query + row * DIM;

    for (int c = seg * 8 + w; c < cnt; c += 8 * RSEG) {
        int idx = g_ci[row * CAP + c];
        const float* kp = keys + (size_t)idx * DIM;
        float s = 0.f;
#pragma unroll
        for (int j = 0; j < 4; ++j) {
            float4 kv = *reinterpret_cast<const float4*>(kp + lane * 16 + j * 4);
            float4 qv = *reinterpret_cast<const float4*>(q + lane * 16 + j * 4);
            s += kv.x * qv.x + kv.y * qv.y + kv.z * qv.z + kv.w * qv.w;
        }
#pragma unroll
        for (int o = 16; o; o >>= 1) s += __shfl_xor_sync(FULLMASK, s, o);
        if (lane == 0) g_cv[row * CAP + c] = s * SCALE_D;
    }
}

// ---------------- warp helpers for exact merge ----------------
__device__ __forceinline__ float warp_min32(float v) {
#pragma unroll
    for (int o = 16; o; o >>= 1) v = fminf(v, __shfl_xor_sync(FULLMASK, v, o));
    return v;
}

__device__ __forceinline__ void topk_insert4(float a0, float a1, float a2, float a3,
                                             int base, float& v0, float& v1,
                                             int& i0, int& i1, float& thr) {
    unsigned pm = (unsigned)(a0 > thr) | ((unsigned)(a1 > thr) << 1) |
                  ((unsigned)(a2 > thr) << 2) | ((unsigned)(a3 > thr) << 3);
    while (__any_sync(FULLMASK, pm != 0)) {
        int c = __ffs(pm) - 1;
        float cv = (c == 0) ? a0 : (c == 1) ? a1 : (c == 2) ? a2 : a3;
        int ci = base + c;
        unsigned ball = __ballot_sync(FULLMASK, pm != 0);
        int src = __ffs(ball) - 1;
        float cand = __shfl_sync(FULLMASK, cv, src);
        int candi = __shfl_sync(FULLMASK, ci, src);
        int lane = threadIdx.x & 31;
        if (lane == src) pm &= pm - 1;
        if (cand > thr) {
            float mn = fminf(v0, v1);
            float wmn = warp_min32(mn);
            unsigned who = __ballot_sync(FULLMASK, mn == wmn);
            int wl = __ffs(who) - 1;
            if (lane == wl) {
                if (v0 <= v1) { v0 = cand; i0 = candi; }
                else          { v1 = cand; i1 = candi; }
            }
            thr = warp_min32(fminf(v0, v1));
        }
        if (pm) {
            if ((pm & 1u) && a0 <= thr) pm &= ~1u;
            if ((pm & 2u) && a1 <= thr) pm &= ~2u;
            if ((pm & 4u) && a2 <= thr) pm &= ~4u;
            if ((pm & 8u) && a3 <= thr) pm &= ~8u;
        }
    }
}

// ---------------- kernel M: exact sorted top-64 from candidates ----------------
__global__ void __launch_bounds__(1024)
k_topk_merge() {
    int row = blockIdx.x;
    int tid = threadIdx.x;
    int lane = tid & 31;
    int wid = tid >> 5;

    int C = g_cnt[row]; if (C > CAP) C = CAP;
    const float* CV = g_cv + (size_t)row * CAP;
    const int*   CI = g_ci + (size_t)row * CAP;

    float v0 = NEG_BIG, v1 = NEG_BIG;
    int i0 = 0, i1 = 0;
    float thr = NEG_BIG;

    int iters = (C + 4095) >> 12;
    for (int it = 0; it < iters; ++it) {
        int f = (it << 12) + (tid << 2);
        float a0 = (f + 0 < C) ? CV[f + 0] : NEG_BIG;
        float a1 = (f + 1 < C) ? CV[f + 1] : NEG_BIG;
        float a2 = (f + 2 < C) ? CV[f + 2] : NEG_BIG;
        float a3 = (f + 3 < C) ? CV[f + 3] : NEG_BIG;
        topk_insert4(a0, a1, a2, a3, f, v0, v1, i0, i1, thr);
    }
    i0 = (v0 > NEG_BIG) ? CI[i0] : 0x7fffffff;
    i1 = (v1 > NEG_BIG) ? CI[i1] : 0x7fffffff;

    __shared__ float sv[2048];
    __shared__ int   si[2048];
    __shared__ float wv[32];
    __shared__ int   wp[32];
    __shared__ int   wsrc[32];
    sv[wid * 64 + lane]      = v0;  si[wid * 64 + lane]      = i0;
    sv[wid * 64 + 32 + lane] = v1;  si[wid * 64 + 32 + lane] = i1;
    __syncthreads();

    for (int j = 0; j < MAXK; ++j) {
        float bv = sv[wid * 64 + lane];      int bi = si[wid * 64 + lane];      int bp = wid * 64 + lane;
        float ov = sv[wid * 64 + 32 + lane]; int oi = si[wid * 64 + 32 + lane]; int op = wid * 64 + 32 + lane;
        if (ov > bv || (ov == bv && oi < bi)) { bv = ov; bi = oi; bp = op; }
#pragma unroll
        for (int o = 16; o; o >>= 1) {
            float xv = __shfl_xor_sync(FULLMASK, bv, o);
            int   xi = __shfl_xor_sync(FULLMASK, bi, o);
            int   xp = __shfl_xor_sync(FULLMASK, bp, o);
            if (xv > bv || (xv == bv && xi < bi)) { bv = xv; bi = xi; bp = xp; }
        }
        if (lane == 0) { wv[wid] = bv; wp[wid] = bi; wsrc[wid] = bp; }
        __syncthreads();
        if (wid == 0) {
            float cv2 = wv[lane]; int ci2 = wp[lane]; int cp2 = wsrc[lane];
#pragma unroll
            for (int o = 16; o; o >>= 1) {
                float xv = __shfl_xor_sync(FULLMASK, cv2, o);
                int   xi = __shfl_xor_sync(FULLMASK, ci2, o);
                int   xp = __shfl_xor_sync(FULLMASK, cp2, o);
                if (xv > cv2 || (xv == cv2 && xi < ci2)) { cv2 = xv; ci2 = xi; cp2 = xp; }
            }
            if (lane == 0) {
                g_topv[row * MAXK + j] = cv2;
                g_topi[row * MAXK + j] = ci2;
                sv[cp2] = NEG_BIG;
                si[cp2] = 0x7fffffff;
            }
        }
        __syncthreads();
    }
}

// ---------------- kernel 5: softmax(top-kd) + gather + weighted sum ----------------
__global__ void k_aggregate(const float* __restrict__ P,
                            const int* __restrict__ kdyn,
                            float* __restrict__ out) {
    int row = blockIdx.x;
    int tid = threadIdx.x;
    __shared__ float ws[MAXK];
    __shared__ int   idx[MAXK];
    __shared__ float s_inv;

    int kd = *kdyn;
    kd = kd < 0 ? 0 : (kd > MAXK ? MAXK : kd);

    if (tid < MAXK) {
        float v = g_topv[row * MAXK + tid];
        idx[tid] = g_topi[row * MAXK + tid];
        float m = (kd > 0) ? g_topv[row * MAXK] : -1e9f;
        float mv = (tid < kd) ? v : -1e9f;
        ws[tid] = expf(mv - m);
    }
    __syncthreads();
    if (tid == 0) {
        float s = 0.f;
#pragma unroll
        for (int j = 0; j < MAXK; ++j) s += ws[j];
        s_inv = 1.0f / s;
    }
    __syncthreads();

    float a = 0.f;
#pragma unroll 4
    for (int j = 0; j < MAXK; ++j) {
        float w = ws[j];
        if (w != 0.f) a += w * P[(size_t)idx[j] * DIM + tid];
    }
    out[row * DIM + tid] = a * s_inv;
}

// ---------------- launcher ----------------
extern "C" void kernel_launch(void* const* d_in, const int* in_sizes, int n_in,
                              void* d_out, int out_size) {
    const float* hidden      = (const float*)d_in[0];
    const float* pool_params = (const float*)d_in[1];
    const float* pool_keys   = (const float*)d_in[2];
    const float* W           = (const float*)d_in[3];
    const float* bias        = (const float*)d_in[4];
    const int*   k_dynamic   = (const int*)d_in[5];
    float* out = (float*)d_out;

    int N = in_sizes[2] / DIM;

    static const size_t SMEMTC = (size_t)(BATCH * QS + TCN * KS) * sizeof(__nv_bfloat16);
    cudaFuncSetAttribute(k_scores_tc, cudaFuncAttributeMaxDynamicSharedMemorySize, (int)SMEMTC);

    int nblk = (N + TCN - 1) / TCN;
    if (nblk > MAXBLK) nblk = MAXBLK;

    k_pool_partial<<<BATCH * 8, 256>>>(hidden);
    k_query<<<BATCH, DIM>>>(W, bias);
    k_scores_tc<<<nblk, 256, SMEMTC>>>(pool_keys, N);
    k_rowmax<<<BATCH, 256>>>(nblk);
    k_filter<<<BATCH * SEGS2, 256>>>(N);
    k_rescore<<<BATCH * RSEG, 256>>>(pool_keys);
    k_topk_merge<<<BATCH, 1024>>>();
    k_aggregate<<<BATCH, DIM>>>(pool_params, k_dynamic, out);
}